// round 13
// baseline (speedup 1.0000x reference)
#include <cuda_runtime.h>
#include <cuda_bf16.h>
#include <cstdint>

typedef unsigned long long ull;

#define NR_MAX 32
#define E_MAX  2000000
#define N_MAX  200000
#define TILE_E 128            // edges per CTA tile (8 warps x 16 edges)
#define T_MAX  (E_MAX / TILE_E + NR_MAX)

// ---------------- scratch (static device globals) ----------------------------
__device__ int g_srcT[E_MAX];             // tile-ordered src node ids
__device__ int g_dstT[E_MAX];             // tile-ordered dst node ids
__device__ int g_counts[NR_MAX];          // zero-init; scan re-zeros after use
__device__ int g_offsets[NR_MAX + 1];
__device__ int g_cursor[NR_MAX];
__device__ int g_tileBase[NR_MAX + 1];
__device__ int4 g_tinfo[T_MAX];           // (r, start, len, 0) per tile
__device__ unsigned g_done;               // k_prep completion counter
// pre-split weights [r][o][f] bf16 (8KB/rel each)
__device__ __align__(16) __nv_bfloat16 g_whi[NR_MAX * 64 * 64];
__device__ __align__(16) __nv_bfloat16 g_wlo[NR_MAX * 64 * 64];
// pre-split features: one 256B row per node = hi[64] | lo[64]
__device__ __align__(16) __nv_bfloat16 g_fsp[N_MAX * 128];

// ---------------- ptx helpers -------------------------------------------------
__device__ __forceinline__ uint32_t smem_u32(const void* p) {
    uint32_t a;
    asm("{ .reg .u64 t; cvta.to.shared.u64 t, %1; cvt.u32.u64 %0, t; }" : "=r"(a) : "l"(p));
    return a;
}
__device__ __forceinline__ void cpa16(uint32_t dst, const void* src, int sz) {
    asm volatile("cp.async.cg.shared.global [%0], [%1], 16, %2;"
                 :: "r"(dst), "l"(src), "r"(sz) : "memory");
}
__device__ __forceinline__ void cpa_commit() {
    asm volatile("cp.async.commit_group;" ::: "memory");
}
__device__ __forceinline__ void cpa_wait1() {
    asm volatile("cp.async.wait_group 1;" ::: "memory");
}
__device__ __forceinline__ void cpa_wait0() {
    asm volatile("cp.async.wait_group 0;" ::: "memory");
}
__device__ __forceinline__ void ldsm4(uint32_t& r0, uint32_t& r1, uint32_t& r2, uint32_t& r3, uint32_t a) {
    asm volatile("ldmatrix.sync.aligned.m8n8.x4.shared.b16 {%0,%1,%2,%3}, [%4];"
                 : "=r"(r0), "=r"(r1), "=r"(r2), "=r"(r3) : "r"(a));
}
__device__ __forceinline__ void mma_bf16(float* d, uint32_t a0, uint32_t a1, uint32_t a2, uint32_t a3,
                                         uint32_t b0, uint32_t b1) {
    asm volatile(
        "mma.sync.aligned.m16n8k16.row.col.f32.bf16.bf16.f32 "
        "{%0,%1,%2,%3}, {%4,%5,%6,%7}, {%8,%9}, {%0,%1,%2,%3};"
        : "+f"(d[0]), "+f"(d[1]), "+f"(d[2]), "+f"(d[3])
        : "r"(a0), "r"(a1), "r"(a2), "r"(a3), "r"(b0), "r"(b1));
}
__device__ __forceinline__ void red4(float* p, float a, float b, float c, float d) {
    asm volatile("red.global.add.v4.f32 [%0], {%1,%2,%3,%4};"
                 :: "l"(p), "f"(a), "f"(b), "f"(c), "f"(d) : "memory");
}

// ---------------- K1: fused prep (+ last-block scan) ---------------------------
__global__ void k_prep(float4* out4, int n4,
                       const float* __restrict__ feat, int NF,
                       const float* __restrict__ weight, int RW,
                       const int* __restrict__ et, int E, int R) {
    int gtid = blockIdx.x * blockDim.x + threadIdx.x;
    int gsz  = gridDim.x * blockDim.x;

    for (int i = gtid; i < n4; i += gsz) out4[i] = make_float4(0.f, 0.f, 0.f, 0.f);

    for (int i = gtid; i < RW; i += gsz) {
        int r = i >> 12, f = (i >> 6) & 63, o = i & 63;
        float w = weight[i];
        __nv_bfloat16 h = __float2bfloat16(w);
        __nv_bfloat16 l = __float2bfloat16(w - __bfloat162float(h));
        g_whi[r * 4096 + o * 64 + f] = h;
        g_wlo[r * 4096 + o * 64 + f] = l;
    }

    for (int i = gtid; i < NF; i += gsz) {
        float v = feat[i];
        int n = i >> 6, f = i & 63;
        __nv_bfloat16 h = __float2bfloat16(v);
        g_fsp[n * 128 + f]      = h;
        g_fsp[n * 128 + 64 + f] = __float2bfloat16(v - __bfloat162float(h));
    }

    __shared__ int h[NR_MAX];
    if (threadIdx.x < NR_MAX) h[threadIdx.x] = 0;
    __syncthreads();
    for (int i = gtid; i < E; i += gsz) atomicAdd(&h[et[i]], 1);
    __syncthreads();
    if (threadIdx.x < NR_MAX && h[threadIdx.x]) atomicAdd(&g_counts[threadIdx.x], h[threadIdx.x]);

    // last block performs the tiny scan
    __threadfence();
    __syncthreads();
    if (threadIdx.x == 0) {
        unsigned prev = atomicAdd(&g_done, 1u);
        if (prev == gridDim.x - 1) {
            g_done = 0;
            int acc = 0, tacc = 0;
            for (int r = 0; r < R; r++) {
                g_offsets[r] = acc; g_cursor[r] = acc; g_tileBase[r] = tacc;
                int c = g_counts[r];
                g_counts[r] = 0;
                acc += c; tacc += (c + TILE_E - 1) / TILE_E;
            }
            g_offsets[R] = acc; g_tileBase[R] = tacc;
            __threadfence();
        }
    }
}

// ---------------- K3: bucket edges (writes src/dst tile-ordered) ---------------
#define SC_CH 2048
__global__ void k_scatter(const int* __restrict__ et,
                          const int* __restrict__ src, const int* __restrict__ dst,
                          int E, int R) {
    __shared__ int h[NR_MAX], base[NR_MAX];
    if (threadIdx.x < NR_MAX) h[threadIdx.x] = 0;
    __syncthreads();
    int b0 = blockIdx.x * SC_CH;
    int myr[8], myrank[8];
#pragma unroll
    for (int j = 0; j < 8; j++) {
        int i = b0 + j * 256 + threadIdx.x;
        myr[j] = -1;
        if (i < E) { myr[j] = et[i]; myrank[j] = atomicAdd(&h[myr[j]], 1); }
    }
    __syncthreads();
    if (threadIdx.x < R && h[threadIdx.x] > 0)
        base[threadIdx.x] = atomicAdd(&g_cursor[threadIdx.x], h[threadIdx.x]);
    __syncthreads();
#pragma unroll
    for (int j = 0; j < 8; j++) {
        int i = b0 + j * 256 + threadIdx.x;
        if (i < E) {
            int pos = base[myr[j]] + myrank[j];
            g_srcT[pos] = src[i];
            g_dstT[pos] = dst[i];
        }
    }

    // piggyback: per-tile info
    int t = blockIdx.x * blockDim.x + threadIdx.x;
    int T = g_tileBase[R];
    if (t < T) {
        int r = 0;
#pragma unroll 1
        for (int i = 1; i < NR_MAX; i++)
            if (i < R && t >= g_tileBase[i]) r = i;
        int start = g_offsets[r] + (t - g_tileBase[r]) * TILE_E;
        int len = min(TILE_E, g_offsets[r + 1] - start);
        g_tinfo[t] = make_int4(r, start, len, 0);
    }
}

// ---------------- K4: warp-autonomous HMMA tile (m16n64 per warp) --------------
// 128B pitch; 16B-chunk index XOR (row & 7) swizzle. ONE barrier (B visibility).
#define OFF_A    0
#define A_HALF   (128 * 128)                // 16384
#define OFF_B    (OFF_A + 2 * A_HALF)       // 32768
#define B_HALF   (64 * 128)                 // 8192
#define SMEM_SZ  (OFF_B + 2 * B_HALF)       // 49152

__global__ __launch_bounds__(256, 4) void k_main(float* __restrict__ out, int R)
{
    extern __shared__ char smem[];
    uint32_t sb = smem_u32(smem);
    int tid = threadIdx.x;
    int wid = tid >> 5, lid = tid & 31;

    int t = blockIdx.x;
    if (t >= g_tileBase[R]) return;
    int4 ti = g_tinfo[t];                   // r, start, len
    int r = ti.x, start = ti.y, len = ti.z;

    // Group 0: B tiles (no index dependency — issued first).
    {
        const char* wh = (const char*)g_whi + (size_t)r * 8192;
        const char* wl = (const char*)g_wlo + (size_t)r * 8192;
#pragma unroll
        for (int j = 0; j < 2; j++) {
            int c = j * 256 + tid;            // 0..511
            int row = c >> 3, col = c & 7;
            uint32_t doff = row * 128 + (((col ^ (row & 7))) << 4);
            cpa16(sb + OFF_B + doff, wh + row * 128 + col * 16, 16);
            cpa16(sb + OFF_B + B_HALF + doff, wl + row * 128 + col * 16, 16);
        }
    }
    cpa_commit();                             // group 0 = B

    // Group 1: this warp's 16 A rows (2 lanes per edge: hi / lo halves).
    int e2 = (wid << 4) + (lid >> 1), half = lid & 1;
    {
        int s = (e2 < len) ? g_srcT[start + e2] : -1;
        const char* fs = (const char*)g_fsp + (size_t)(s >= 0 ? s : 0) * 256 + half * 128;
        int sz = (s >= 0) ? 16 : 0;
        uint32_t da = sb + OFF_A + half * A_HALF + e2 * 128;
        int r7 = e2 & 7;
#pragma unroll
        for (int c = 0; c < 8; c++) cpa16(da + ((c ^ r7) << 4), fs + c * 16, sz);
    }
    cpa_commit();                             // group 1 = A(own warp)

    cpa_wait1();                              // own B part done
    __syncthreads();                          // B globally visible — ONLY barrier
    cpa_wait0();                              // own A rows done
    __syncwarp();                             // warp-scope visibility of A

    // m16n64 per warp: acc[8 n-tiles][4]
    float acc[8][4];
#pragma unroll
    for (int a = 0; a < 8; a++)
#pragma unroll
        for (int b = 0; b < 4; b++) acc[a][b] = 0.f;

    int rA = (wid << 4) + (lid & 15);
    int rA7 = rA & 7;
    int cA0 = lid >> 4;
    int rowBb = (lid & 7) + ((lid >> 4) << 3);
    int cB0 = (lid >> 3) & 1;

#pragma unroll
    for (int kk = 0; kk < 4; kk++) {
        uint32_t aoff = (uint32_t)(((cA0 + 2 * kk) ^ rA7) << 4);
        uint32_t aAddr = sb + OFF_A + (uint32_t)rA * 128 + aoff;
        uint32_t aH0, aH1, aH2, aH3, aL0, aL1, aL2, aL3;
        ldsm4(aH0, aH1, aH2, aH3, aAddr);
        ldsm4(aL0, aL1, aL2, aL3, aAddr + A_HALF);
#pragma unroll
        for (int nt = 0; nt < 4; nt++) {      // n16 tiles
            int rowB = rowBb + nt * 16;
            uint32_t bAddr = sb + OFF_B + (uint32_t)rowB * 128
                           + (uint32_t)(((cB0 + 2 * kk) ^ (rowB & 7)) << 4);
            uint32_t bh0, bh1, bh2, bh3, bl0, bl1, bl2, bl3;
            ldsm4(bh0, bh1, bh2, bh3, bAddr);
            ldsm4(bl0, bl1, bl2, bl3, bAddr + B_HALF);
            mma_bf16(acc[2 * nt],     aH0, aH1, aH2, aH3, bh0, bh1);
            mma_bf16(acc[2 * nt],     aH0, aH1, aH2, aH3, bl0, bl1);
            mma_bf16(acc[2 * nt],     aL0, aL1, aL2, aL3, bh0, bh1);
            mma_bf16(acc[2 * nt + 1], aH0, aH1, aH2, aH3, bh2, bh3);
            mma_bf16(acc[2 * nt + 1], aH0, aH1, aH2, aH3, bl2, bl3);
            mma_bf16(acc[2 * nt + 1], aL0, aL1, aL2, aL3, bh2, bh3);
        }
    }

    // Epilogue: shfl.xor(1) pair repack -> 16B red.global.add.v4 per n-tile
    int g = lid >> 2, tig = lid & 3;
    bool even = (tig & 1) == 0;
    int cb = even ? (tig * 2) : ((tig - 1) * 2);
    int row = (wid << 4) + g + (even ? 0 : 8);
    bool live = row < len;
    float* pbase = out;
    if (live) pbase = out + (size_t)g_dstT[start + row] * 64 + cb;
#pragma unroll
    for (int nt = 0; nt < 8; nt++) {
        float o0 = __shfl_xor_sync(0xffffffffu, acc[nt][0], 1);
        float o1 = __shfl_xor_sync(0xffffffffu, acc[nt][1], 1);
        float o2 = __shfl_xor_sync(0xffffffffu, acc[nt][2], 1);
        float o3 = __shfl_xor_sync(0xffffffffu, acc[nt][3], 1);
        if (live) {
            if (even) red4(pbase + nt * 8, acc[nt][0], acc[nt][1], o0, o1);
            else      red4(pbase + nt * 8, o2, o3, acc[nt][2], acc[nt][3]);
        }
    }
}

// ---------------- launch ------------------------------------------------------
extern "C" void kernel_launch(void* const* d_in, const int* in_sizes, int n_in,
                              void* d_out, int out_size) {
    const float* feat   = (const float*)d_in[0];
    const float* weight = (const float*)d_in[1];
    const int*   src    = (const int*)d_in[2];
    const int*   dst    = (const int*)d_in[3];
    const int*   et     = (const int*)d_in[4];
    float*       out    = (float*)d_out;

    int NF = in_sizes[0];
    int RW = in_sizes[1];
    int E  = in_sizes[2];
    int R  = RW / 4096;
    if (R < 1) R = 1;
    if (R > NR_MAX) R = NR_MAX;

    cudaFuncSetAttribute(k_main, cudaFuncAttributeMaxDynamicSharedMemorySize, SMEM_SZ);

    int n4 = out_size / 4;
    k_prep<<<1184, 256>>>((float4*)d_out, n4, feat, NF, weight, RW, et, E, R);
    k_scatter<<<(E + SC_CH - 1) / SC_CH, 256>>>(et, src, dst, E, R);

    int maxTiles = (E + TILE_E - 1) / TILE_E + R;
    k_main<<<maxTiles, 256, SMEM_SZ>>>(out, R);
}

// round 14
// speedup vs baseline: 1.0357x; 1.0357x over previous
#include <cuda_runtime.h>
#include <cuda_bf16.h>
#include <cstdint>

typedef unsigned long long ull;

#define NR_MAX 32
#define E_MAX  2000000
#define N_MAX  200000
#define TILE_E 128            // edges per MMA tile (M=128)
#define T_MAX  (E_MAX / TILE_E + NR_MAX)

// ---------------- scratch (static device globals) ----------------------------
__device__ int g_srcT[E_MAX];             // tile-ordered src node ids
__device__ int g_dstT[E_MAX];             // tile-ordered dst node ids
__device__ int g_counts[NR_MAX];          // zero-init; scan re-zeros after use
__device__ int g_offsets[NR_MAX + 1];
__device__ int g_cursor[NR_MAX];
__device__ int g_tileBase[NR_MAX + 1];
__device__ int4 g_tinfo[T_MAX];           // (r, start, len, 0) per tile
__device__ unsigned g_done;               // k_prep completion counter
// pre-split weights [r][o][f] bf16 (8KB/rel each)
__device__ __align__(16) __nv_bfloat16 g_whi[NR_MAX * 64 * 64];
__device__ __align__(16) __nv_bfloat16 g_wlo[NR_MAX * 64 * 64];
// pre-split features: one 256B row per node = hi[64] | lo[64]
__device__ __align__(16) __nv_bfloat16 g_fsp[N_MAX * 128];

// ---------------- ptx helpers -------------------------------------------------
__device__ __forceinline__ uint32_t smem_u32(const void* p) {
    uint32_t a;
    asm("{ .reg .u64 t; cvta.to.shared.u64 t, %1; cvt.u32.u64 %0, t; }" : "=r"(a) : "l"(p));
    return a;
}
__device__ __forceinline__ void cpa16(uint32_t dst, const void* src, int sz) {
    asm volatile("cp.async.cg.shared.global [%0], [%1], 16, %2;"
                 :: "r"(dst), "l"(src), "r"(sz) : "memory");
}
__device__ __forceinline__ void cpa_commit() {
    asm volatile("cp.async.commit_group;" ::: "memory");
}
__device__ __forceinline__ void cpa_wait1() {
    asm volatile("cp.async.wait_group 1;" ::: "memory");
}
__device__ __forceinline__ void cpa_wait0() {
    asm volatile("cp.async.wait_group 0;" ::: "memory");
}
__device__ __forceinline__ void ldsm4(uint32_t& r0, uint32_t& r1, uint32_t& r2, uint32_t& r3, uint32_t a) {
    asm volatile("ldmatrix.sync.aligned.m8n8.x4.shared.b16 {%0,%1,%2,%3}, [%4];"
                 : "=r"(r0), "=r"(r1), "=r"(r2), "=r"(r3) : "r"(a));
}
__device__ __forceinline__ void mma_bf16(float* d, uint32_t a0, uint32_t a1, uint32_t a2, uint32_t a3,
                                         uint32_t b0, uint32_t b1) {
    asm volatile(
        "mma.sync.aligned.m16n8k16.row.col.f32.bf16.bf16.f32 "
        "{%0,%1,%2,%3}, {%4,%5,%6,%7}, {%8,%9}, {%0,%1,%2,%3};"
        : "+f"(d[0]), "+f"(d[1]), "+f"(d[2]), "+f"(d[3])
        : "r"(a0), "r"(a1), "r"(a2), "r"(a3), "r"(b0), "r"(b1));
}
__device__ __forceinline__ void red2(float* p, float a, float b) {
    asm volatile("red.global.add.v2.f32 [%0], {%1,%2};"
                 :: "l"(p), "f"(a), "f"(b) : "memory");
}

// pack 4 floats -> 4 bf16 (hi) and 4 bf16 (lo residual), each as uint2 (8B)
__device__ __forceinline__ void split4(float4 v, uint2& hp, uint2& lp) {
    __nv_bfloat16 hx = __float2bfloat16(v.x), hy = __float2bfloat16(v.y);
    __nv_bfloat16 hz = __float2bfloat16(v.z), hw = __float2bfloat16(v.w);
    hp.x = (uint32_t)__bfloat16_as_ushort(hx) | ((uint32_t)__bfloat16_as_ushort(hy) << 16);
    hp.y = (uint32_t)__bfloat16_as_ushort(hz) | ((uint32_t)__bfloat16_as_ushort(hw) << 16);
    __nv_bfloat16 lx = __float2bfloat16(v.x - __bfloat162float(hx));
    __nv_bfloat16 ly = __float2bfloat16(v.y - __bfloat162float(hy));
    __nv_bfloat16 lz = __float2bfloat16(v.z - __bfloat162float(hz));
    __nv_bfloat16 lw = __float2bfloat16(v.w - __bfloat162float(hw));
    lp.x = (uint32_t)__bfloat16_as_ushort(lx) | ((uint32_t)__bfloat16_as_ushort(ly) << 16);
    lp.y = (uint32_t)__bfloat16_as_ushort(lz) | ((uint32_t)__bfloat16_as_ushort(lw) << 16);
}

// ---------------- K1: fused prep (vectorized, + last-block scan) ---------------
__global__ void k_prep(float4* out4, int n4,
                       const float4* __restrict__ feat4, int NF4,   // NF/4
                       const float4* __restrict__ weight4, int RW4, // RW/4
                       const int* __restrict__ et, int E, int R) {
    int gtid = blockIdx.x * blockDim.x + threadIdx.x;
    int gsz  = gridDim.x * blockDim.x;

    // zero output (16B stores)
    for (int i = gtid; i < n4; i += gsz) out4[i] = make_float4(0.f, 0.f, 0.f, 0.f);

    // split + transpose weights: [r][f][o] fp32 -> [r][o][f] bf16 hi/lo
    // one float4 = 4 consecutive o for fixed (r, f)
    for (int i = gtid; i < RW4; i += gsz) {
        float4 w = weight4[i];
        int r = i >> 10, rem = i & 1023;      // 1024 float4 per relation
        int f = rem >> 4, o0 = (rem & 15) * 4;
        uint2 hp, lp;
        split4(w, hp, lp);
        __nv_bfloat16* bh = g_whi + r * 4096 + f;
        __nv_bfloat16* bl = g_wlo + r * 4096 + f;
        ushort2 h2 = *(ushort2*)&hp.x, h3 = *(ushort2*)&hp.y;
        ushort2 l2 = *(ushort2*)&lp.x, l3 = *(ushort2*)&lp.y;
        bh[(o0 + 0) * 64] = __ushort_as_bfloat16(h2.x);
        bh[(o0 + 1) * 64] = __ushort_as_bfloat16(h2.y);
        bh[(o0 + 2) * 64] = __ushort_as_bfloat16(h3.x);
        bh[(o0 + 3) * 64] = __ushort_as_bfloat16(h3.y);
        bl[(o0 + 0) * 64] = __ushort_as_bfloat16(l2.x);
        bl[(o0 + 1) * 64] = __ushort_as_bfloat16(l2.y);
        bl[(o0 + 2) * 64] = __ushort_as_bfloat16(l3.x);
        bl[(o0 + 3) * 64] = __ushort_as_bfloat16(l3.y);
    }

    // split features: float4 load -> 8B hi store + 8B lo store
    for (int i = gtid; i < NF4; i += gsz) {
        float4 v = feat4[i];
        int n = i >> 4, c = i & 15;           // node, float4-chunk (16 per node)
        uint2 hp, lp;
        split4(v, hp, lp);
        uint2* base = (uint2*)(g_fsp + (size_t)n * 128);
        base[c]      = hp;                    // hi half: bytes [0,128)
        base[16 + c] = lp;                    // lo half: bytes [128,256)
    }

    // histogram (int4 loads)
    __shared__ int h[NR_MAX];
    if (threadIdx.x < NR_MAX) h[threadIdx.x] = 0;
    __syncthreads();
    int E4 = E >> 2;
    const int4* et4 = (const int4*)et;
    for (int i = gtid; i < E4; i += gsz) {
        int4 e = et4[i];
        atomicAdd(&h[e.x], 1); atomicAdd(&h[e.y], 1);
        atomicAdd(&h[e.z], 1); atomicAdd(&h[e.w], 1);
    }
    for (int i = E4 * 4 + gtid; i < E; i += gsz) atomicAdd(&h[et[i]], 1);
    __syncthreads();
    if (threadIdx.x < NR_MAX && h[threadIdx.x]) atomicAdd(&g_counts[threadIdx.x], h[threadIdx.x]);

    // last block performs the tiny scan
    __threadfence();
    __syncthreads();
    if (threadIdx.x == 0) {
        unsigned prev = atomicAdd(&g_done, 1u);
        if (prev == gridDim.x - 1) {
            g_done = 0;
            int acc = 0, tacc = 0;
            for (int r = 0; r < R; r++) {
                g_offsets[r] = acc; g_cursor[r] = acc; g_tileBase[r] = tacc;
                int c = g_counts[r];
                g_counts[r] = 0;
                acc += c; tacc += (c + TILE_E - 1) / TILE_E;
            }
            g_offsets[R] = acc; g_tileBase[R] = tacc;
            __threadfence();
        }
    }
}

// ---------------- K3: bucket edges (writes src/dst tile-ordered) ---------------
#define SC_CH 2048
__global__ void k_scatter(const int* __restrict__ et,
                          const int* __restrict__ src, const int* __restrict__ dst,
                          int E, int R) {
    __shared__ int h[NR_MAX], base[NR_MAX];
    if (threadIdx.x < NR_MAX) h[threadIdx.x] = 0;
    __syncthreads();
    int b0 = blockIdx.x * SC_CH;
    int myr[8], myrank[8];
#pragma unroll
    for (int j = 0; j < 8; j++) {
        int i = b0 + j * 256 + threadIdx.x;
        myr[j] = -1;
        if (i < E) { myr[j] = et[i]; myrank[j] = atomicAdd(&h[myr[j]], 1); }
    }
    __syncthreads();
    if (threadIdx.x < R && h[threadIdx.x] > 0)
        base[threadIdx.x] = atomicAdd(&g_cursor[threadIdx.x], h[threadIdx.x]);
    __syncthreads();
#pragma unroll
    for (int j = 0; j < 8; j++) {
        int i = b0 + j * 256 + threadIdx.x;
        if (i < E) {
            int pos = base[myr[j]] + myrank[j];
            g_srcT[pos] = src[i];
            g_dstT[pos] = dst[i];
        }
    }

    // piggyback: per-tile info
    int t = blockIdx.x * blockDim.x + threadIdx.x;
    int T = g_tileBase[R];
    if (t < T) {
        int r = 0;
#pragma unroll 1
        for (int i = 1; i < NR_MAX; i++)
            if (i < R && t >= g_tileBase[i]) r = i;
        int start = g_offsets[r] + (t - g_tileBase[r]) * TILE_E;
        int len = min(TILE_E, g_offsets[r + 1] - start);
        g_tinfo[t] = make_int4(r, start, len, 0);
    }
}

// ---------------- K4: HMMA grouped-GEMM tile (m32n32 warps, split-commit) ------
// 128B pitch; 16B-chunk index XOR (row & 7) swizzle.
#define OFF_A    0
#define A_HALF   (128 * 128)                // 16384
#define OFF_B    (OFF_A + 2 * A_HALF)       // 32768
#define B_HALF   (64 * 128)                 // 8192
#define SMEM_SZ  (OFF_B + 2 * B_HALF)       // 49152

__global__ __launch_bounds__(256, 4) void k_main(float* __restrict__ out, int R)
{
    extern __shared__ char smem[];
    uint32_t sb = smem_u32(smem);
    int tid = threadIdx.x;
    int wid = tid >> 5, lid = tid & 31;

    int t = blockIdx.x;
    if (t >= g_tileBase[R]) return;
    int4 ti = g_tinfo[t];                   // r, start, len
    int r = ti.x, start = ti.y, len = ti.z;

    // Phase A: gather. Group 0 = A cols 0..31 (chunks 0..3) + full B.
    //          Group 1 = A cols 32..63 (chunks 4..7).
    int e2 = tid >> 1, half = tid & 1;
    {
        int s = (e2 < len) ? g_srcT[start + e2] : -1;
        const char* fs = (const char*)g_fsp + (size_t)(s >= 0 ? s : 0) * 256 + half * 128;
        int sz = (s >= 0) ? 16 : 0;
        uint32_t da = sb + OFF_A + half * A_HALF + e2 * 128;
        int r7 = e2 & 7;
#pragma unroll
        for (int c = 0; c < 4; c++) cpa16(da + ((c ^ r7) << 4), fs + c * 16, sz);
        // B tiles: 512 hi + 512 lo 16B chunks (swizzled), 2+2 per thread
        {
            const char* wh = (const char*)g_whi + (size_t)r * 8192;
            const char* wl = (const char*)g_wlo + (size_t)r * 8192;
#pragma unroll
            for (int j = 0; j < 2; j++) {
                int c = j * 256 + tid;            // 0..511
                int row = c >> 3, col = c & 7;
                uint32_t doff = row * 128 + (((col ^ (row & 7))) << 4);
                cpa16(sb + OFF_B + doff, wh + row * 128 + col * 16, 16);
                cpa16(sb + OFF_B + B_HALF + doff, wl + row * 128 + col * 16, 16);
            }
        }
        cpa_commit();                          // group 0
#pragma unroll
        for (int c = 4; c < 8; c++) cpa16(da + ((c ^ r7) << 4), fs + c * 16, sz);
        cpa_commit();                          // group 1
    }

    // m32n32 warp layout: rowg = wid>>1 (4 groups), colg = wid&1 (2 groups)
    int rowg = wid >> 1, colg = wid & 1;
    float acc[2][4][4];
#pragma unroll
    for (int a = 0; a < 2; a++)
#pragma unroll
        for (int b = 0; b < 4; b++)
#pragma unroll
            for (int c = 0; c < 4; c++) acc[a][b][c] = 0.f;

    int rA0 = rowg * 32 + (lid & 15);
    int rA7 = rA0 & 7;                        // same parity for rt offset 16
    int cA0 = lid >> 4;
    int rowBb = colg * 32 + (lid & 7) + ((lid >> 4) << 3);
    int cB0 = (lid >> 3) & 1;

    cpa_wait1();                              // group 0 (A cols 0..31 + B) done
    __syncthreads();

#pragma unroll
    for (int kh = 0; kh < 2; kh++) {          // k halves
        if (kh == 1) {                        // wait for A cols 32..63
            cpa_wait0();
            __syncthreads();
        }
#pragma unroll
        for (int ki = 0; ki < 2; ki++) {
            int kk = kh * 2 + ki;
            // hoist B fragments for this kk (both p, hi+lo)
            uint32_t bh[2][4], bl[2][4];
#pragma unroll
            for (int p = 0; p < 2; p++) {
                int rowB = rowBb + p * 16;
                uint32_t bAddr = sb + OFF_B + (uint32_t)rowB * 128
                               + (uint32_t)(((cB0 + 2 * kk) ^ (rowB & 7)) << 4);
                ldsm4(bh[p][0], bh[p][1], bh[p][2], bh[p][3], bAddr);
                ldsm4(bl[p][0], bl[p][1], bl[p][2], bl[p][3], bAddr + B_HALF);
            }
            uint32_t aoff = (uint32_t)(((cA0 + 2 * kk) ^ rA7) << 4);
#pragma unroll
            for (int rt = 0; rt < 2; rt++) {
                uint32_t aAddr = sb + OFF_A + (uint32_t)(rA0 + rt * 16) * 128 + aoff;
                uint32_t aH0, aH1, aH2, aH3, aL0, aL1, aL2, aL3;
                ldsm4(aH0, aH1, aH2, aH3, aAddr);
                ldsm4(aL0, aL1, aL2, aL3, aAddr + A_HALF);
#pragma unroll
                for (int p = 0; p < 2; p++) {
                    mma_bf16(acc[rt][2 * p],     aH0, aH1, aH2, aH3, bh[p][0], bh[p][1]);
                    mma_bf16(acc[rt][2 * p],     aH0, aH1, aH2, aH3, bl[p][0], bl[p][1]);
                    mma_bf16(acc[rt][2 * p],     aL0, aL1, aL2, aL3, bh[p][0], bh[p][1]);
                    mma_bf16(acc[rt][2 * p + 1], aH0, aH1, aH2, aH3, bh[p][2], bh[p][3]);
                    mma_bf16(acc[rt][2 * p + 1], aH0, aH1, aH2, aH3, bl[p][2], bl[p][3]);
                    mma_bf16(acc[rt][2 * p + 1], aL0, aL1, aL2, aL3, bh[p][2], bh[p][3]);
                }
            }
        }
    }

    // Epilogue: direct v2 reductions from fragment layout (dst read from g_dstT)
    int g = lid >> 2, tig = lid & 3;
    int colb = colg * 32 + tig * 2;
#pragma unroll
    for (int rt = 0; rt < 2; rt++) {
        int row0 = rowg * 32 + rt * 16 + g;
        int row1 = row0 + 8;
        bool l0 = row0 < len, l1 = row1 < len;
        float* p0 = out;
        float* p1 = out;
        if (l0) p0 = out + (size_t)g_dstT[start + row0] * 64 + colb;
        if (l1) p1 = out + (size_t)g_dstT[start + row1] * 64 + colb;
#pragma unroll
        for (int nt = 0; nt < 4; nt++) {
            if (l0) red2(p0 + nt * 8, acc[rt][nt][0], acc[rt][nt][1]);
            if (l1) red2(p1 + nt * 8, acc[rt][nt][2], acc[rt][nt][3]);
        }
    }
}

// ---------------- launch ------------------------------------------------------
extern "C" void kernel_launch(void* const* d_in, const int* in_sizes, int n_in,
                              void* d_out, int out_size) {
    const float* feat   = (const float*)d_in[0];
    const float* weight = (const float*)d_in[1];
    const int*   src    = (const int*)d_in[2];
    const int*   dst    = (const int*)d_in[3];
    const int*   et     = (const int*)d_in[4];
    float*       out    = (float*)d_out;

    int NF = in_sizes[0];
    int RW = in_sizes[1];
    int E  = in_sizes[2];
    int R  = RW / 4096;
    if (R < 1) R = 1;
    if (R > NR_MAX) R = NR_MAX;

    cudaFuncSetAttribute(k_main, cudaFuncAttributeMaxDynamicSharedMemorySize, SMEM_SZ);

    int n4 = out_size / 4;
    k_prep<<<1184, 256>>>((float4*)d_out, n4, (const float4*)feat, NF / 4,
                          (const float4*)weight, RW / 4, et, E, R);
    k_scatter<<<(E + SC_CH - 1) / SC_CH, 256>>>(et, src, dst, E, R);

    int maxTiles = (E + TILE_E - 1) / TILE_E + R;
    k_main<<<maxTiles, 256, SMEM_SZ>>>(out, R);
}

// round 16
// speedup vs baseline: 1.0433x; 1.0074x over previous
#include <cuda_runtime.h>
#include <cuda_bf16.h>
#include <cstdint>

typedef unsigned long long ull;

#define NR_MAX 32
#define E_MAX  2000000
#define N_MAX  200000
#define TILE_E 128            // edges per MMA tile (M=128)
#define T_MAX  (E_MAX / TILE_E + NR_MAX)

// ---------------- scratch (static device globals) ----------------------------
__device__ int g_srcT[E_MAX];             // tile-ordered src node ids
__device__ int g_dstT[E_MAX];             // tile-ordered dst node ids
__device__ int g_counts[NR_MAX];          // zero-init; scan re-zeros after use
__device__ int g_offsets[NR_MAX + 1];
__device__ int g_cursor[NR_MAX];
__device__ int g_tileBase[NR_MAX + 1];
__device__ int4 g_tinfo[T_MAX];           // (r, start, len, 0) per tile
__device__ unsigned g_done;               // k_prep completion counter
// pre-split weights [r][o][f] bf16 (8KB/rel each)
__device__ __align__(16) __nv_bfloat16 g_whi[NR_MAX * 64 * 64];
__device__ __align__(16) __nv_bfloat16 g_wlo[NR_MAX * 64 * 64];
// pre-split features: one 256B row per node = hi[64] | lo[64]
__device__ __align__(16) __nv_bfloat16 g_fsp[N_MAX * 128];

// ---------------- ptx helpers -------------------------------------------------
__device__ __forceinline__ uint32_t smem_u32(const void* p) {
    uint32_t a;
    asm("{ .reg .u64 t; cvta.to.shared.u64 t, %1; cvt.u32.u64 %0, t; }" : "=r"(a) : "l"(p));
    return a;
}
__device__ __forceinline__ void cpa16(uint32_t dst, const void* src, int sz) {
    asm volatile("cp.async.cg.shared.global [%0], [%1], 16, %2;"
                 :: "r"(dst), "l"(src), "r"(sz) : "memory");
}
__device__ __forceinline__ void cpa_commit() {
    asm volatile("cp.async.commit_group;" ::: "memory");
}
__device__ __forceinline__ void cpa_wait1() {
    asm volatile("cp.async.wait_group 1;" ::: "memory");
}
__device__ __forceinline__ void cpa_wait0() {
    asm volatile("cp.async.wait_group 0;" ::: "memory");
}
__device__ __forceinline__ void ldsm4(uint32_t& r0, uint32_t& r1, uint32_t& r2, uint32_t& r3, uint32_t a) {
    asm volatile("ldmatrix.sync.aligned.m8n8.x4.shared.b16 {%0,%1,%2,%3}, [%4];"
                 : "=r"(r0), "=r"(r1), "=r"(r2), "=r"(r3) : "r"(a));
}
__device__ __forceinline__ void mma_bf16(float* d, uint32_t a0, uint32_t a1, uint32_t a2, uint32_t a3,
                                         uint32_t b0, uint32_t b1) {
    asm volatile(
        "mma.sync.aligned.m16n8k16.row.col.f32.bf16.bf16.f32 "
        "{%0,%1,%2,%3}, {%4,%5,%6,%7}, {%8,%9}, {%0,%1,%2,%3};"
        : "+f"(d[0]), "+f"(d[1]), "+f"(d[2]), "+f"(d[3])
        : "r"(a0), "r"(a1), "r"(a2), "r"(a3), "r"(b0), "r"(b1));
}
__device__ __forceinline__ void red2(float* p, float a, float b) {
    asm volatile("red.global.add.v2.f32 [%0], {%1,%2};"
                 :: "l"(p), "f"(a), "f"(b) : "memory");
}

// pack 4 floats -> 4 bf16 (hi) and 4 bf16 (lo residual), each as uint2 (8B)
__device__ __forceinline__ void split4(float4 v, uint2& hp, uint2& lp) {
    __nv_bfloat16 hx = __float2bfloat16(v.x), hy = __float2bfloat16(v.y);
    __nv_bfloat16 hz = __float2bfloat16(v.z), hw = __float2bfloat16(v.w);
    hp.x = (uint32_t)__bfloat16_as_ushort(hx) | ((uint32_t)__bfloat16_as_ushort(hy) << 16);
    hp.y = (uint32_t)__bfloat16_as_ushort(hz) | ((uint32_t)__bfloat16_as_ushort(hw) << 16);
    __nv_bfloat16 lx = __float2bfloat16(v.x - __bfloat162float(hx));
    __nv_bfloat16 ly = __float2bfloat16(v.y - __bfloat162float(hy));
    __nv_bfloat16 lz = __float2bfloat16(v.z - __bfloat162float(hz));
    __nv_bfloat16 lw = __float2bfloat16(v.w - __bfloat162float(hw));
    lp.x = (uint32_t)__bfloat16_as_ushort(lx) | ((uint32_t)__bfloat16_as_ushort(ly) << 16);
    lp.y = (uint32_t)__bfloat16_as_ushort(lz) | ((uint32_t)__bfloat16_as_ushort(lw) << 16);
}

// ---------------- K1: fused prep (vectorized, + last-block scan) ---------------
__global__ void k_prep(float4* out4, int n4,
                       const float4* __restrict__ feat4, int NF4,   // NF/4
                       const float4* __restrict__ weight4, int RW4, // RW/4
                       const int* __restrict__ et, int E, int R) {
    int gtid = blockIdx.x * blockDim.x + threadIdx.x;
    int gsz  = gridDim.x * blockDim.x;

    // zero output (16B stores)
    for (int i = gtid; i < n4; i += gsz) out4[i] = make_float4(0.f, 0.f, 0.f, 0.f);

    // split + transpose weights: [r][f][o] fp32 -> [r][o][f] bf16 hi/lo
    for (int i = gtid; i < RW4; i += gsz) {
        float4 w = weight4[i];
        int r = i >> 10, rem = i & 1023;      // 1024 float4 per relation
        int f = rem >> 4, o0 = (rem & 15) * 4;
        uint2 hp, lp;
        split4(w, hp, lp);
        __nv_bfloat16* bh = g_whi + r * 4096 + f;
        __nv_bfloat16* bl = g_wlo + r * 4096 + f;
        ushort2 h2 = *(ushort2*)&hp.x, h3 = *(ushort2*)&hp.y;
        ushort2 l2 = *(ushort2*)&lp.x, l3 = *(ushort2*)&lp.y;
        bh[(o0 + 0) * 64] = __ushort_as_bfloat16(h2.x);
        bh[(o0 + 1) * 64] = __ushort_as_bfloat16(h2.y);
        bh[(o0 + 2) * 64] = __ushort_as_bfloat16(h3.x);
        bh[(o0 + 3) * 64] = __ushort_as_bfloat16(h3.y);
        bl[(o0 + 0) * 64] = __ushort_as_bfloat16(l2.x);
        bl[(o0 + 1) * 64] = __ushort_as_bfloat16(l2.y);
        bl[(o0 + 2) * 64] = __ushort_as_bfloat16(l3.x);
        bl[(o0 + 3) * 64] = __ushort_as_bfloat16(l3.y);
    }

    // split features: float4 load -> 8B hi store + 8B lo store
    for (int i = gtid; i < NF4; i += gsz) {
        float4 v = feat4[i];
        int n = i >> 4, c = i & 15;
        uint2 hp, lp;
        split4(v, hp, lp);
        uint2* base = (uint2*)(g_fsp + (size_t)n * 128);
        base[c]      = hp;
        base[16 + c] = lp;
    }

    // histogram (int4 loads)
    __shared__ int h[NR_MAX];
    if (threadIdx.x < NR_MAX) h[threadIdx.x] = 0;
    __syncthreads();
    int E4 = E >> 2;
    const int4* et4 = (const int4*)et;
    for (int i = gtid; i < E4; i += gsz) {
        int4 e = et4[i];
        atomicAdd(&h[e.x], 1); atomicAdd(&h[e.y], 1);
        atomicAdd(&h[e.z], 1); atomicAdd(&h[e.w], 1);
    }
    for (int i = E4 * 4 + gtid; i < E; i += gsz) atomicAdd(&h[et[i]], 1);
    __syncthreads();
    if (threadIdx.x < NR_MAX && h[threadIdx.x]) atomicAdd(&g_counts[threadIdx.x], h[threadIdx.x]);

    // last block performs the tiny scan
    __threadfence();
    __syncthreads();
    if (threadIdx.x == 0) {
        unsigned prev = atomicAdd(&g_done, 1u);
        if (prev == gridDim.x - 1) {
            g_done = 0;
            int acc = 0, tacc = 0;
            for (int r = 0; r < R; r++) {
                g_offsets[r] = acc; g_cursor[r] = acc; g_tileBase[r] = tacc;
                int c = g_counts[r];
                g_counts[r] = 0;
                acc += c; tacc += (c + TILE_E - 1) / TILE_E;
            }
            g_offsets[R] = acc; g_tileBase[R] = tacc;
            __threadfence();
        }
    }
}

// ---------------- K3: bucket edges (writes src/dst tile-ordered) ---------------
#define SC_CH 2048
__global__ void k_scatter(const int* __restrict__ et,
                          const int* __restrict__ src, const int* __restrict__ dst,
                          int E, int R) {
    __shared__ int h[NR_MAX], base[NR_MAX];
    if (threadIdx.x < NR_MAX) h[threadIdx.x] = 0;
    __syncthreads();
    int b0 = blockIdx.x * SC_CH;
    int myr[8], myrank[8];
#pragma unroll
    for (int j = 0; j < 8; j++) {
        int i = b0 + j * 256 + threadIdx.x;
        myr[j] = -1;
        if (i < E) { myr[j] = et[i]; myrank[j] = atomicAdd(&h[myr[j]], 1); }
    }
    __syncthreads();
    if (threadIdx.x < R && h[threadIdx.x] > 0)
        base[threadIdx.x] = atomicAdd(&g_cursor[threadIdx.x], h[threadIdx.x]);
    __syncthreads();
#pragma unroll
    for (int j = 0; j < 8; j++) {
        int i = b0 + j * 256 + threadIdx.x;
        if (i < E) {
            int pos = base[myr[j]] + myrank[j];
            g_srcT[pos] = src[i];
            g_dstT[pos] = dst[i];
        }
    }

    // piggyback: per-tile info
    int t = blockIdx.x * blockDim.x + threadIdx.x;
    int T = g_tileBase[R];
    if (t < T) {
        int r = 0;
#pragma unroll 1
        for (int i = 1; i < NR_MAX; i++)
            if (i < R && t >= g_tileBase[i]) r = i;
        int start = g_offsets[r] + (t - g_tileBase[r]) * TILE_E;
        int len = min(TILE_E, g_offsets[r + 1] - start);
        g_tinfo[t] = make_int4(r, start, len, 0);
    }
}

// ---------------- K4: HMMA grouped-GEMM tile (m32n32 warps, split-commit) ------
// 128B pitch; 16B-chunk index XOR (row & 7) swizzle. dst staged in smem.
#define OFF_DST  0                          // int[128]
#define OFF_A    1024
#define A_HALF   (128 * 128)                // 16384
#define OFF_B    (OFF_A + 2 * A_HALF)       // 33792
#define B_HALF   (64 * 128)                 // 8192
#define SMEM_SZ  (OFF_B + 2 * B_HALF)       // 50176

__global__ __launch_bounds__(256, 4) void k_main(float* __restrict__ out, int R)
{
    extern __shared__ char smem[];
    uint32_t sb = smem_u32(smem);
    int tid = threadIdx.x;
    int wid = tid >> 5, lid = tid & 31;

    int t = blockIdx.x;
    if (t >= g_tileBase[R]) return;
    int4 ti = g_tinfo[t];                   // r, start, len
    int r = ti.x, start = ti.y, len = ti.z;

    int* dsts = (int*)(smem + OFF_DST);

    // Phase A: gather. Group 0 = A cols 0..31 (chunks 0..3) + full B.
    //          Group 1 = A cols 32..63 (chunks 4..7).
    // dst staged into smem here (coalesced read, latency hidden by cpa waits).
    int e2 = tid >> 1, half = tid & 1;
    {
        int s = -1;
        if (e2 < len) {
            s = g_srcT[start + e2];                      // coalesced
            if (half == 0) dsts[e2] = g_dstT[start + e2]; // coalesced
        }
        const char* fs = (const char*)g_fsp + (size_t)(s >= 0 ? s : 0) * 256 + half * 128;
        int sz = (s >= 0) ? 16 : 0;
        uint32_t da = sb + OFF_A + half * A_HALF + e2 * 128;
        int r7 = e2 & 7;
#pragma unroll
        for (int c = 0; c < 4; c++) cpa16(da + ((c ^ r7) << 4), fs + c * 16, sz);
        // B tiles: 512 hi + 512 lo 16B chunks (swizzled), 2+2 per thread
        {
            const char* wh = (const char*)g_whi + (size_t)r * 8192;
            const char* wl = (const char*)g_wlo + (size_t)r * 8192;
#pragma unroll
            for (int j = 0; j < 2; j++) {
                int c = j * 256 + tid;            // 0..511
                int row = c >> 3, col = c & 7;
                uint32_t doff = row * 128 + (((col ^ (row & 7))) << 4);
                cpa16(sb + OFF_B + doff, wh + row * 128 + col * 16, 16);
                cpa16(sb + OFF_B + B_HALF + doff, wl + row * 128 + col * 16, 16);
            }
        }
        cpa_commit();                          // group 0
#pragma unroll
        for (int c = 4; c < 8; c++) cpa16(da + ((c ^ r7) << 4), fs + c * 16, sz);
        cpa_commit();                          // group 1
    }

    // m32n32 warp layout: rowg = wid>>1 (4 groups), colg = wid&1 (2 groups)
    int rowg = wid >> 1, colg = wid & 1;
    float acc[2][4][4];
#pragma unroll
    for (int a = 0; a < 2; a++)
#pragma unroll
        for (int b = 0; b < 4; b++)
#pragma unroll
            for (int c = 0; c < 4; c++) acc[a][b][c] = 0.f;

    int rA0 = rowg * 32 + (lid & 15);
    int rA7 = rA0 & 7;                        // same parity for rt offset 16
    int cA0 = lid >> 4;
    int rowBb = colg * 32 + (lid & 7) + ((lid >> 4) << 3);
    int cB0 = (lid >> 3) & 1;

    cpa_wait1();                              // group 0 (A cols 0..31 + B) done
    __syncthreads();

#pragma unroll
    for (int kh = 0; kh < 2; kh++) {          // k halves
        if (kh == 1) {                        // wait for A cols 32..63
            cpa_wait0();
            __syncthreads();
        }
#pragma unroll
        for (int ki = 0; ki < 2; ki++) {
            int kk = kh * 2 + ki;
            // hoist B fragments for this kk (both p, hi+lo)
            uint32_t bh[2][4], bl[2][4];
#pragma unroll
            for (int p = 0; p < 2; p++) {
                int rowB = rowBb + p * 16;
                uint32_t bAddr = sb + OFF_B + (uint32_t)rowB * 128
                               + (uint32_t)(((cB0 + 2 * kk) ^ (rowB & 7)) << 4);
                ldsm4(bh[p][0], bh[p][1], bh[p][2], bh[p][3], bAddr);
                ldsm4(bl[p][0], bl[p][1], bl[p][2], bl[p][3], bAddr + B_HALF);
            }
            uint32_t aoff = (uint32_t)(((cA0 + 2 * kk) ^ rA7) << 4);
#pragma unroll
            for (int rt = 0; rt < 2; rt++) {
                uint32_t aAddr = sb + OFF_A + (uint32_t)(rA0 + rt * 16) * 128 + aoff;
                uint32_t aH0, aH1, aH2, aH3, aL0, aL1, aL2, aL3;
                ldsm4(aH0, aH1, aH2, aH3, aAddr);
                ldsm4(aL0, aL1, aL2, aL3, aAddr + A_HALF);
#pragma unroll
                for (int p = 0; p < 2; p++) {
                    mma_bf16(acc[rt][2 * p],     aH0, aH1, aH2, aH3, bh[p][0], bh[p][1]);
                    mma_bf16(acc[rt][2 * p],     aH0, aH1, aH2, aH3, bl[p][0], bl[p][1]);
                    mma_bf16(acc[rt][2 * p],     aL0, aL1, aL2, aL3, bh[p][0], bh[p][1]);
                    mma_bf16(acc[rt][2 * p + 1], aH0, aH1, aH2, aH3, bh[p][2], bh[p][3]);
                    mma_bf16(acc[rt][2 * p + 1], aH0, aH1, aH2, aH3, bl[p][2], bl[p][3]);
                    mma_bf16(acc[rt][2 * p + 1], aL0, aL1, aL2, aL3, bh[p][2], bh[p][3]);
                }
            }
        }
    }

    // Epilogue: direct v2 reductions from fragment layout (dst from smem)
    int g = lid >> 2, tig = lid & 3;
    int colb = colg * 32 + tig * 2;
#pragma unroll
    for (int rt = 0; rt < 2; rt++) {
        int row0 = rowg * 32 + rt * 16 + g;
        int row1 = row0 + 8;
        bool l0 = row0 < len, l1 = row1 < len;
        float* p0 = l0 ? (out + (size_t)dsts[row0] * 64 + colb) : out;
        float* p1 = l1 ? (out + (size_t)dsts[row1] * 64 + colb) : out;
#pragma unroll
        for (int nt = 0; nt < 4; nt++) {
            if (l0) red2(p0 + nt * 8, acc[rt][nt][0], acc[rt][nt][1]);
            if (l1) red2(p1 + nt * 8, acc[rt][nt][2], acc[rt][nt][3]);
        }
    }
}

// ---------------- launch ------------------------------------------------------
extern "C" void kernel_launch(void* const* d_in, const int* in_sizes, int n_in,
                              void* d_out, int out_size) {
    const float* feat   = (const float*)d_in[0];
    const float* weight = (const float*)d_in[1];
    const int*   src    = (const int*)d_in[2];
    const int*   dst    = (const int*)d_in[3];
    const int*   et     = (const int*)d_in[4];
    float*       out    = (float*)d_out;

    int NF = in_sizes[0];
    int RW = in_sizes[1];
    int E  = in_sizes[2];
    int R  = RW / 4096;
    if (R < 1) R = 1;
    if (R > NR_MAX) R = NR_MAX;

    cudaFuncSetAttribute(k_main, cudaFuncAttributeMaxDynamicSharedMemorySize, SMEM_SZ);

    int n4 = out_size / 4;
    k_prep<<<1184, 256>>>((float4*)d_out, n4, (const float4*)feat, NF / 4,
                          (const float4*)weight, RW / 4, et, E, R);
    k_scatter<<<(E + SC_CH - 1) / SC_CH, 256>>>(et, src, dst, E, R);

    int maxTiles = (E + TILE_E - 1) / TILE_E + R;
    k_main<<<maxTiles, 256, SMEM_SZ>>>(out, R);
}